// round 16
// baseline (speedup 1.0000x reference)
#include <cuda_runtime.h>
#include <cuda_fp16.h>
#include <cstdint>
#include <math.h>

// NeuralODE via mma.sync m16n8k16 FP16 + BULK async copy (cp.async.bulk, one
// instruction per 2-4KB strip) + mbarrier producer/consumer pipeline.
// h_{n+1} = h_n + 0.1 * tanh(h_n @ W[k]^T + b[k]), k = n/10, n = 0..99, B=D=1024.
// R16: replaces 2048 per-thread cp.async per CTA-stage with 12 bulk copies
// issued by one thread -> LSU issue pressure collapses. CTA 64x64, 256 thr
// (2m x 2n x 2k), BK=128, 3-slot ring (96KB) + mbarriers, 2 CTAs/SM, grid 256.

#define D_DIM   1024
#define BM      64
#define BN      64
#define THREADS 256
#define KITERS  8
#define STAGES  3

#define A_WORDS 4096                 // 64 rows x 128 k fp16 = 16KB
#define B_WORDS 4096                 // 64 n x 128 k fp16 = 16KB
#define STAGE_WORDS (A_WORDS + B_WORDS)      // 8192 words = 32KB
#define STAGE_BYTES (STAGE_WORDS * 4)
#define MBAR_OFF  (STAGES * STAGE_BYTES)     // 98304
#define SMEM_BYTES (MBAR_OFF + 64)           // 98368

__device__ uint32_t g_Wh[10u * 512u * 1024u];   // W fp16, k32-fused B-block layout
__device__ uint32_t g_Hh[2][512u * 1024u];      // H fp16 ping-pong, A-block layout

__device__ __forceinline__ uint32_t pack2(float a, float b) {
    __half2 h = __floats2half2_rn(a, b);
    return *reinterpret_cast<uint32_t*>(&h);
}

__device__ __forceinline__ void mma_f16(float c[4],
                                        uint32_t a0, uint32_t a1,
                                        uint32_t a2, uint32_t a3,
                                        uint32_t b0, uint32_t b1) {
    asm volatile(
        "mma.sync.aligned.m16n8k16.row.col.f32.f16.f16.f32 "
        "{%0,%1,%2,%3}, {%4,%5,%6,%7}, {%8,%9}, {%0,%1,%2,%3};"
        : "+f"(c[0]), "+f"(c[1]), "+f"(c[2]), "+f"(c[3])
        : "r"(a0), "r"(a1), "r"(a2), "r"(a3), "r"(b0), "r"(b1));
}

__device__ __forceinline__ float fast_tanh(float x) {
    float ax = fabsf(x);
    float t = __expf(-2.0f * ax);
    float r = __fdividef(1.0f - t, 1.0f + t);
    return copysignf(r, x);
}

__device__ __forceinline__ uint32_t smem_u32(const void* p) {
    uint32_t a;
    asm("{ .reg .u64 t; cvta.to.shared.u64 t, %1; cvt.u32.u64 %0, t; }"
        : "=r"(a) : "l"(p));
    return a;
}

#define MBAR_INIT(addr, cnt) \
    asm volatile("mbarrier.init.shared.b64 [%0], %1;" :: "r"(addr), "r"(cnt) : "memory")
#define MBAR_EXPECT_TX(addr, bytes) \
    asm volatile("mbarrier.arrive.expect_tx.shared.b64 _, [%0], %1;" \
                 :: "r"(addr), "r"(bytes) : "memory")
#define MBAR_ARRIVE(addr) \
    asm volatile("mbarrier.arrive.shared.b64 _, [%0];" :: "r"(addr) : "memory")
#define CP_BULK(dst, src, bytes, mbar) \
    asm volatile("cp.async.bulk.shared::cta.global.mbarrier::complete_tx::bytes " \
                 "[%0], [%1], %2, [%3];" \
                 :: "r"(dst), "l"(src), "r"(bytes), "r"(mbar) : "memory")

__device__ __forceinline__ void mbar_wait(uint32_t mbar, uint32_t parity) {
    uint32_t done;
    asm volatile("{\n\t.reg .pred p;\n\t"
                 "mbarrier.try_wait.parity.acquire.cta.shared::cta.b64 p, [%1], %2;\n\t"
                 "selp.b32 %0, 1, 0, p;\n\t}"
                 : "=r"(done) : "r"(mbar), "r"(parity) : "memory");
    if (!done) {
        asm volatile("{\n\t.reg .pred P1;\n\t"
                     "WL_%=:\n\t"
                     "mbarrier.try_wait.parity.acquire.cta.shared::cta.b64 P1, [%0], %1, 0x989680;\n\t"
                     "@P1 bra.uni WD_%=;\n\t"
                     "bra.uni WL_%=;\n\t"
                     "WD_%=:\n\t}"
                     :: "r"(mbar), "r"(parity) : "memory");
    }
}

// ---- W convert: fp16 k32-fused B-block layout (verified R14/R15) ----
__global__ void convert_W(const float* __restrict__ W, uint32_t* __restrict__ out)
{
    const int nquads = 10 * 512 * 1024 / 4;
    for (int q = blockIdx.x * blockDim.x + threadIdx.x; q < nquads;
         q += gridDim.x * blockDim.x) {
        uint32_t blk  = (uint32_t)q >> 5;
        uint32_t lane = (uint32_t)q & 31;
        uint32_t slab = blk >> 12;
        uint32_t rem  = blk & 4095u;
        uint32_t nb = rem >> 5, kq = rem & 31u;
        uint32_t g = lane >> 2, tig = lane & 3;
        const float* s = W + (size_t)slab * 1048576u
                           + (size_t)(nb * 8 + g) * 1024u + kq * 32 + tig * 2;
        uint4 v;
        v.x = pack2(s[0],  s[1]);
        v.y = pack2(s[8],  s[9]);
        v.z = pack2(s[16], s[17]);
        v.w = pack2(s[24], s[25]);
        *reinterpret_cast<uint4*>(out + (size_t)q * 4) = v;
    }
}

// ---- X convert: fp16 A-block layout (verified R14/R15) ----
__global__ void convert_X(const float* __restrict__ x, uint32_t* __restrict__ out)
{
    const int nquads = 512 * 1024 / 4;
    for (int q = blockIdx.x * blockDim.x + threadIdx.x; q < nquads;
         q += gridDim.x * blockDim.x) {
        uint32_t blk  = (uint32_t)q >> 5;
        uint32_t lane = (uint32_t)q & 31;
        uint32_t rb = blk >> 6, kb = blk & 63u;
        uint32_t g = lane >> 2, tig = lane & 3;
        const float* s = x + (size_t)(rb * 16 + g) * 1024u + kb * 16 + tig * 2;
        uint4 v;
        v.x = pack2(s[0],        s[1]);
        v.y = pack2(s[8192],     s[8193]);
        v.z = pack2(s[8],        s[9]);
        v.w = pack2(s[8192 + 8], s[8192 + 9]);
        *reinterpret_cast<uint4*>(out + (size_t)q * 4) = v;
    }
}

__global__ __launch_bounds__(THREADS, 2)
void ode_step(const uint32_t* __restrict__ Ah,    // H fp16, A-block layout
              const uint32_t* __restrict__ Bh,    // W slab fp16, k32-fused layout
              const float*    __restrict__ Hfp,   // traj[n] fp32 row-major
              const float*    __restrict__ bk,
              float*          __restrict__ Hout,  // traj[n+1] fp32 row-major
              uint32_t*       __restrict__ Houth) // next H fp16, A-block layout
{
    extern __shared__ uint32_t smem[];
    const uint32_t sbase = smem_u32(smem);

    const int tid  = threadIdx.x;
    const int wid  = tid >> 5;
    const int lane = tid & 31;
    const int g    = lane >> 2;
    const int tig  = lane & 3;
    const int wm   = wid & 1;        // 2 warp rows of 32
    const int wn   = (wid >> 1) & 1; // 2 warp cols of 32
    const int ks   = wid >> 2;       // k-split half
    const int bm   = blockIdx.y * BM;
    const int bn   = blockIdx.x * BN;
    const int rb0  = blockIdx.y * 4;  // A 16-row block base
    const int nb0  = blockIdx.x * 8;  // B 8-col block base

    // mbarriers: full[i] at MBAR_OFF + i*16, empty[i] at +8
    const uint32_t mb = sbase + MBAR_OFF;
    if (tid == 0) {
#pragma unroll
        for (int i = 0; i < STAGES; i++) {
            MBAR_INIT(mb + i * 16, 1);       // full: producer expect_tx arrive
            MBAR_INIT(mb + i * 16 + 8, 8);   // empty: 8 warp arrivals
        }
    }
    __syncthreads();

    // producer: 12 bulk copies per stage (4x4KB A strips + 8x2KB B strips)
    auto produce = [&](int s, int slot) {
        const uint32_t fullb = mb + slot * 16;
        const uint32_t dst0  = sbase + (uint32_t)slot * STAGE_BYTES;
        MBAR_EXPECT_TX(fullb, (uint32_t)STAGE_BYTES);
#pragma unroll
        for (int rbl = 0; rbl < 4; rbl++) {
            const uint32_t* src = Ah + ((size_t)(rb0 + rbl) * 64 + s * 8) * 128;
            CP_BULK(dst0 + rbl * 4096u, src, 4096u, fullb);
        }
#pragma unroll
        for (int nbl = 0; nbl < 8; nbl++) {
            const uint32_t* src = Bh + ((size_t)(nb0 + nbl) * 32 + s * 4) * 128;
            CP_BULK(dst0 + A_WORDS * 4 + nbl * 2048u, src, 2048u, fullb);
        }
    };

    float acc[2][4][4];
#pragma unroll
    for (int mt = 0; mt < 2; mt++)
#pragma unroll
        for (int nt = 0; nt < 4; nt++)
#pragma unroll
            for (int r = 0; r < 4; r++) acc[mt][nt][r] = 0.0f;

    uint32_t fa[2][2][4];   // [buf][mt][a0..a3]
    uint4    fbp[2][4];     // [buf][nt] = {b0_r0, b1_r0, b0_r1, b1_r1}

    auto loadA = [&](const uint32_t* __restrict__ st, int jl, int p) {
#pragma unroll
        for (int mt = 0; mt < 2; mt++) {
            uint4 v = *reinterpret_cast<const uint4*>(
                st + ((wm * 2 + mt) * 8 + jl) * 128 + lane * 4);
            fa[p][mt][0] = v.x; fa[p][mt][1] = v.y;
            fa[p][mt][2] = v.z; fa[p][mt][3] = v.w;
        }
    };
    auto loadB = [&](const uint32_t* __restrict__ st, int kql, int pr) {
#pragma unroll
        for (int nt = 0; nt < 4; nt++) {
            fbp[pr][nt] = *reinterpret_cast<const uint4*>(
                st + A_WORDS + ((wn * 4 + nt) * 4 + kql) * 128 + lane * 4);
        }
    };
    auto do_mma = [&](int p, int pr, int r) {
#pragma unroll
        for (int mt = 0; mt < 2; mt++)
#pragma unroll
            for (int nt = 0; nt < 4; nt++) {
                uint32_t b0 = r ? fbp[pr][nt].z : fbp[pr][nt].x;
                uint32_t b1 = r ? fbp[pr][nt].w : fbp[pr][nt].y;
                mma_f16(acc[mt][nt],
                        fa[p][mt][0], fa[p][mt][1], fa[p][mt][2], fa[p][mt][3],
                        b0, b1);
            }
    };

    // producer cursor (tid 0): phase starts 1 so first empty-waits pass
    int pslot = 0, pphase = 1;
    auto prod_step = [&](int s) {
        mbar_wait(mb + pslot * 16 + 8, (uint32_t)pphase);   // empty[pslot]
        produce(s, pslot);
        if (++pslot == STAGES) { pslot = 0; pphase ^= 1; }
    };

    // ---- prologue: produce stages 0,1 ----
    if (tid == 0) { prod_step(0); prod_step(1); }

    const int jl0 = ks * 4;
    const int kqb = ks * 2;
    int cslot = 0, cphase = 0;
    for (int s = 0; s < KITERS; s++) {
        mbar_wait(mb + cslot * 16, (uint32_t)cphase);       // full[cslot]

        const uint32_t* st = smem + cslot * STAGE_WORDS;

        loadA(st, jl0 + 0, 0);
        loadB(st, kqb + 0, 0);

        if (tid == 0 && s + 2 < KITERS) prod_step(s + 2);

        loadA(st, jl0 + 1, 1);
        do_mma(0, 0, 0);
        loadA(st, jl0 + 2, 0);
        loadB(st, kqb + 1, 1);
        do_mma(1, 0, 1);
        loadA(st, jl0 + 3, 1);
        do_mma(0, 1, 0);
        do_mma(1, 1, 1);

        if (lane == 0) MBAR_ARRIVE(mb + cslot * 16 + 8);    // empty[cslot]
        if (++cslot == STAGES) { cslot = 0; cphase ^= 1; }
    }

    // ---- k-split reduction (exchange buffer = 16KB at smem base) ----
    __syncthreads();   // all warps past mainloop; smem slots reusable
    float* ex = reinterpret_cast<float*>(smem);
    const int p = wid & 3;
    if (ks == 0) {
#pragma unroll
        for (int mt = 0; mt < 2; mt++)
#pragma unroll
            for (int nh = 0; nh < 2; nh++) {
                int q = mt * 2 + nh;
                float4 v = { acc[mt][2 + nh][0], acc[mt][2 + nh][1],
                             acc[mt][2 + nh][2], acc[mt][2 + nh][3] };
                *reinterpret_cast<float4*>(ex + (p * 4 + q) * 128 + lane * 4) = v;
            }
    } else {
#pragma unroll
        for (int mt = 0; mt < 2; mt++)
#pragma unroll
            for (int nh = 0; nh < 2; nh++) {
                int q = mt * 2 + nh;
                float4 v = { acc[mt][nh][0], acc[mt][nh][1],
                             acc[mt][nh][2], acc[mt][nh][3] };
                *reinterpret_cast<float4*>(ex + 2048 + (p * 4 + q) * 128 + lane * 4) = v;
            }
    }
    __syncthreads();
    const int ntb = ks ? 2 : 0;
    const int exo = ks ? 0 : 2048;
#pragma unroll
    for (int mt = 0; mt < 2; mt++)
#pragma unroll
        for (int nh = 0; nh < 2; nh++) {
            int q = mt * 2 + nh;
            float4 v = *reinterpret_cast<const float4*>(
                ex + exo + (p * 4 + q) * 128 + lane * 4);
            acc[mt][ntb + nh][0] += v.x;
            acc[mt][ntb + nh][1] += v.y;
            acc[mt][ntb + nh][2] += v.z;
            acc[mt][ntb + nh][3] += v.w;
        }

    // ---- fused epilogue: fp32 traj + packed fp16 scatter (verified R14/R15) ----
#pragma unroll
    for (int mt = 0; mt < 2; mt++) {
#pragma unroll
        for (int nh = 0; nh < 2; nh++) {
            const int nt = ntb + nh;
            const int R = bm + wm * 32 + mt * 16 + g;
            const int C = bn + wn * 32 + nt * 8 + tig * 2;
            const float b0 = __ldg(&bk[C]);
            const float b1 = __ldg(&bk[C + 1]);

            float2 h0 = *reinterpret_cast<const float2*>(&Hfp[(size_t)R * D_DIM + C]);
            float2 h1 = *reinterpret_cast<const float2*>(&Hfp[(size_t)(R + 8) * D_DIM + C]);
            float o0 = h0.x + 0.1f * fast_tanh(acc[mt][nt][0] + b0);
            float o1 = h0.y + 0.1f * fast_tanh(acc[mt][nt][1] + b1);
            float o2 = h1.x + 0.1f * fast_tanh(acc[mt][nt][2] + b0);
            float o3 = h1.y + 0.1f * fast_tanh(acc[mt][nt][3] + b1);
            *reinterpret_cast<float2*>(&Hout[(size_t)R * D_DIM + C]) = make_float2(o0, o1);
            *reinterpret_cast<float2*>(&Hout[(size_t)(R + 8) * D_DIM + C]) = make_float2(o2, o3);

            const int rb = R >> 4, kb = C >> 4;
            const int c2 = ((nt & 1) << 2) + tig;
            const int lt = g * 4 + (c2 & 3);
            const int wo = (c2 >= 4) ? 2 : 0;
            uint32_t* base = Houth + ((size_t)rb * 64 + kb) * 128 + lt * 4 + wo;
            uint2 u = { pack2(o0, o1), pack2(o2, o3) };
            *reinterpret_cast<uint2*>(base) = u;
        }
    }
}

extern "C" void kernel_launch(void* const* d_in, const int* in_sizes, int n_in,
                              void* d_out, int out_size)
{
    (void)in_sizes; (void)n_in; (void)out_size;
    const float* x = (const float*)d_in[0];   // [1024, 1024]
    const float* W = (const float*)d_in[1];   // [10, 1024, 1024]
    const float* b = (const float*)d_in[2];   // [10, 1024]

    float* out  = (float*)d_out;
    const size_t BD  = (size_t)D_DIM * D_DIM;
    const size_t BDH = BD / 2;
    float* feat = out;
    float* traj = out + BD;

    uint32_t *wh = nullptr, *hh = nullptr;
    cudaGetSymbolAddress((void**)&wh, g_Wh);
    cudaGetSymbolAddress((void**)&hh, g_Hh);
    uint32_t* hh0 = hh;
    uint32_t* hh1 = hh + BDH;

    cudaFuncSetAttribute(ode_step,
                         cudaFuncAttributeMaxDynamicSharedMemorySize, SMEM_BYTES);

    convert_W<<<4096, 256>>>(W, wh);
    convert_X<<<1024, 256>>>(x, hh0);
    cudaMemcpyAsync(traj, x, BD * sizeof(float), cudaMemcpyDeviceToDevice, 0);

    dim3 grid(D_DIM / BN, D_DIM / BM);   // (16, 16) = 256 CTAs
    dim3 block(THREADS);

    for (int n = 0; n < 100; n++) {
        int k = n / 10;
        uint32_t* hin  = (n & 1) ? hh1 : hh0;
        uint32_t* hnew = (n & 1) ? hh0 : hh1;
        ode_step<<<grid, block, SMEM_BYTES, 0>>>(
            hin,
            wh + (size_t)k * BDH,
            traj + (size_t)n * BD,
            b + (size_t)k * D_DIM,
            traj + (size_t)(n + 1) * BD,
            hnew);
    }

    cudaMemcpyAsync(feat, traj + (size_t)100 * BD, BD * sizeof(float),
                    cudaMemcpyDeviceToDevice, 0);
}

// round 17
// speedup vs baseline: 1.1209x; 1.1209x over previous
#include <cuda_runtime.h>
#include <cuda_fp16.h>
#include <cstdint>
#include <math.h>

// NeuralODE via mma.sync m16n8k16 FP16, cp.async ring, fragment-block layouts,
// + Programmatic Dependent Launch: step n+1's CTAs launch while step n drains,
// pre-issue their W loads (no dependency), and gridDepSync only before A loads.
// h_{n+1} = h_n + 0.1 * tanh(h_n @ W[k]^T + b[k]), k = n/10, n = 0..99, B=D=1024.
// R17 = R15 (BK=128, 3-stage ring, CTA 64x64, 2m x 2n x 2k, 2 CTAs/SM) + PDL.

#define D_DIM   1024
#define BM      64
#define BN      64
#define THREADS 256
#define KITERS  8
#define STAGES  3

#define A_WORDS 4096                 // 64 rows x 128 k fp16 = 16KB
#define B_WORDS 4096                 // 64 n x 128 k fp16 = 16KB
#define STAGE_WORDS (A_WORDS + B_WORDS)      // 8192
#define SMEM_BYTES (STAGES * STAGE_WORDS * 4)  // 98304

__device__ uint32_t g_Wh[10u * 512u * 1024u];   // W fp16, k32-fused B-block layout
__device__ uint32_t g_Hh[2][512u * 1024u];      // H fp16 ping-pong, A-block layout

__device__ __forceinline__ uint32_t pack2(float a, float b) {
    __half2 h = __floats2half2_rn(a, b);
    return *reinterpret_cast<uint32_t*>(&h);
}

__device__ __forceinline__ void mma_f16(float c[4],
                                        uint32_t a0, uint32_t a1,
                                        uint32_t a2, uint32_t a3,
                                        uint32_t b0, uint32_t b1) {
    asm volatile(
        "mma.sync.aligned.m16n8k16.row.col.f32.f16.f16.f32 "
        "{%0,%1,%2,%3}, {%4,%5,%6,%7}, {%8,%9}, {%0,%1,%2,%3};"
        : "+f"(c[0]), "+f"(c[1]), "+f"(c[2]), "+f"(c[3])
        : "r"(a0), "r"(a1), "r"(a2), "r"(a3), "r"(b0), "r"(b1));
}

__device__ __forceinline__ float fast_tanh(float x) {
    float ax = fabsf(x);
    float t = __expf(-2.0f * ax);
    float r = __fdividef(1.0f - t, 1.0f + t);
    return copysignf(r, x);
}

__device__ __forceinline__ uint32_t smem_u32(const void* p) {
    uint32_t a;
    asm("{ .reg .u64 t; cvta.to.shared.u64 t, %1; cvt.u32.u64 %0, t; }"
        : "=r"(a) : "l"(p));
    return a;
}

#define CP_ASYNC(dst, src) \
    asm volatile("cp.async.cg.shared.global [%0], [%1], 16;" \
                 :: "r"(dst), "l"(src) : "memory")
#define CP_COMMIT() asm volatile("cp.async.commit_group;" ::: "memory")
#define CP_WAIT1()  asm volatile("cp.async.wait_group 1;" ::: "memory")

// ---- W convert: fp16 k32-fused B-block layout (verified R14-R16) ----
__global__ void convert_W(const float* __restrict__ W, uint32_t* __restrict__ out)
{
    const int nquads = 10 * 512 * 1024 / 4;
    for (int q = blockIdx.x * blockDim.x + threadIdx.x; q < nquads;
         q += gridDim.x * blockDim.x) {
        uint32_t blk  = (uint32_t)q >> 5;
        uint32_t lane = (uint32_t)q & 31;
        uint32_t slab = blk >> 12;
        uint32_t rem  = blk & 4095u;
        uint32_t nb = rem >> 5, kq = rem & 31u;
        uint32_t g = lane >> 2, tig = lane & 3;
        const float* s = W + (size_t)slab * 1048576u
                           + (size_t)(nb * 8 + g) * 1024u + kq * 32 + tig * 2;
        uint4 v;
        v.x = pack2(s[0],  s[1]);
        v.y = pack2(s[8],  s[9]);
        v.z = pack2(s[16], s[17]);
        v.w = pack2(s[24], s[25]);
        *reinterpret_cast<uint4*>(out + (size_t)q * 4) = v;
    }
}

// ---- X convert: fp16 A-block layout (verified R14-R16) ----
__global__ void convert_X(const float* __restrict__ x, uint32_t* __restrict__ out)
{
    const int nquads = 512 * 1024 / 4;
    for (int q = blockIdx.x * blockDim.x + threadIdx.x; q < nquads;
         q += gridDim.x * blockDim.x) {
        uint32_t blk  = (uint32_t)q >> 5;
        uint32_t lane = (uint32_t)q & 31;
        uint32_t rb = blk >> 6, kb = blk & 63u;
        uint32_t g = lane >> 2, tig = lane & 3;
        const float* s = x + (size_t)(rb * 16 + g) * 1024u + kb * 16 + tig * 2;
        uint4 v;
        v.x = pack2(s[0],        s[1]);
        v.y = pack2(s[8192],     s[8193]);
        v.z = pack2(s[8],        s[9]);
        v.w = pack2(s[8192 + 8], s[8192 + 9]);
        *reinterpret_cast<uint4*>(out + (size_t)q * 4) = v;
    }
}

__global__ __launch_bounds__(THREADS, 2)
void ode_step(const uint32_t* __restrict__ Ah,    // H fp16, A-block layout
              const uint32_t* __restrict__ Bh,    // W slab fp16, k32-fused layout
              const float*    __restrict__ Hfp,   // traj[n] fp32 row-major
              const float*    __restrict__ bk,
              float*          __restrict__ Hout,  // traj[n+1] fp32 row-major
              uint32_t*       __restrict__ Houth) // next H fp16, A-block layout
{
    extern __shared__ uint32_t smem[];
    const uint32_t sbase = smem_u32(smem);

    const int tid  = threadIdx.x;
    const int wid  = tid >> 5;
    const int lane = tid & 31;
    const int g    = lane >> 2;
    const int tig  = lane & 3;
    const int wm   = wid & 1;        // 2 warp rows of 32
    const int wn   = (wid >> 1) & 1; // 2 warp cols of 32
    const int ks   = wid >> 2;       // k-split half
    const int bm   = blockIdx.y * BM;
    const int bn   = blockIdx.x * BN;
    const int rb0  = blockIdx.y * 4;  // A 16-row block base
    const int nb0  = blockIdx.x * 8;  // B 8-col block base

    auto issueA = [&](int s, int slot) {
        const uint32_t sst = sbase + (uint32_t)(slot * STAGE_WORDS) * 4u;
#pragma unroll
        for (int i = 0; i < 4; i++) {
            int c = tid + i * THREADS;
            int rbl = c >> 8, j = c & 255;
            const uint32_t* src = Ah + ((size_t)(rb0 + rbl) * 64 + s * 8) * 128 + j * 4;
            CP_ASYNC(sst + (uint32_t)(rbl * 1024 + j * 4) * 4u, src);
        }
    };
    auto issueB = [&](int s, int slot) {
        const uint32_t sst = sbase + (uint32_t)(slot * STAGE_WORDS) * 4u;
#pragma unroll
        for (int i = 0; i < 4; i++) {
            int c = tid + i * THREADS;
            int nbl = c >> 7, j = c & 127;
            const uint32_t* src = Bh + ((size_t)(nb0 + nbl) * 32 + s * 4) * 128 + j * 4;
            CP_ASYNC(sst + (uint32_t)(A_WORDS + nbl * 512 + j * 4) * 4u, src);
        }
    };

    float acc[2][4][4];
#pragma unroll
    for (int mt = 0; mt < 2; mt++)
#pragma unroll
        for (int nt = 0; nt < 4; nt++)
#pragma unroll
            for (int r = 0; r < 4; r++) acc[mt][nt][r] = 0.0f;

    uint32_t fa[2][2][4];
    uint4    fbp[2][4];

    auto loadA = [&](const uint32_t* __restrict__ st, int jl, int p) {
#pragma unroll
        for (int mt = 0; mt < 2; mt++) {
            uint4 v = *reinterpret_cast<const uint4*>(
                st + ((wm * 2 + mt) * 8 + jl) * 128 + lane * 4);
            fa[p][mt][0] = v.x; fa[p][mt][1] = v.y;
            fa[p][mt][2] = v.z; fa[p][mt][3] = v.w;
        }
    };
    auto loadB = [&](const uint32_t* __restrict__ st, int kql, int pr) {
#pragma unroll
        for (int nt = 0; nt < 4; nt++) {
            fbp[pr][nt] = *reinterpret_cast<const uint4*>(
                st + A_WORDS + ((wn * 4 + nt) * 4 + kql) * 128 + lane * 4);
        }
    };
    auto do_mma = [&](int p, int pr, int r) {
#pragma unroll
        for (int mt = 0; mt < 2; mt++)
#pragma unroll
            for (int nt = 0; nt < 4; nt++) {
                uint32_t b0 = r ? fbp[pr][nt].z : fbp[pr][nt].x;
                uint32_t b1 = r ? fbp[pr][nt].w : fbp[pr][nt].y;
                mma_f16(acc[mt][nt],
                        fa[p][mt][0], fa[p][mt][1], fa[p][mt][2], fa[p][mt][3],
                        b0, b1);
            }
    };

    // ---- PDL prologue: W loads need no dependency; A loads wait on upstream ----
    issueB(0, 0);
    issueB(1, 1);
    cudaGridDependencySynchronize();     // upstream epilogue writes (Houth, traj[n]) visible
    issueA(0, 0); CP_COMMIT();           // group g0 = {B0, B1, A0}
    issueA(1, 1); CP_COMMIT();           // group g1 = {A1}

    const int jl0 = ks * 4;
    const int kqb = ks * 2;
    int slot = 0, nslot = 2;
    for (int s = 0; s < KITERS; s++) {
        CP_WAIT1();
        __syncthreads();

        const uint32_t* st = smem + slot * STAGE_WORDS;

        loadA(st, jl0 + 0, 0);
        loadB(st, kqb + 0, 0);

        if (s + 2 < KITERS) { issueA(s + 2, nslot); issueB(s + 2, nslot); }
        CP_COMMIT();

        loadA(st, jl0 + 1, 1);
        do_mma(0, 0, 0);
        loadA(st, jl0 + 2, 0);
        loadB(st, kqb + 1, 1);
        do_mma(1, 0, 1);
        loadA(st, jl0 + 3, 1);
        do_mma(0, 1, 0);
        do_mma(1, 1, 1);

        slot = slot + 1 == STAGES ? 0 : slot + 1;
        nslot = nslot + 1 == STAGES ? 0 : nslot + 1;
    }

    // ---- k-split reduction (verified R14-R16) ----
    __syncthreads();
    float* ex = reinterpret_cast<float*>(smem);
    const int p = wid & 3;
    if (ks == 0) {
#pragma unroll
        for (int mt = 0; mt < 2; mt++)
#pragma unroll
            for (int nh = 0; nh < 2; nh++) {
                int q = mt * 2 + nh;
                float4 v = { acc[mt][2 + nh][0], acc[mt][2 + nh][1],
                             acc[mt][2 + nh][2], acc[mt][2 + nh][3] };
                *reinterpret_cast<float4*>(ex + (p * 4 + q) * 128 + lane * 4) = v;
            }
    } else {
#pragma unroll
        for (int mt = 0; mt < 2; mt++)
#pragma unroll
            for (int nh = 0; nh < 2; nh++) {
                int q = mt * 2 + nh;
                float4 v = { acc[mt][nh][0], acc[mt][nh][1],
                             acc[mt][nh][2], acc[mt][nh][3] };
                *reinterpret_cast<float4*>(ex + 2048 + (p * 4 + q) * 128 + lane * 4) = v;
            }
    }
    __syncthreads();
    const int ntb = ks ? 2 : 0;
    const int exo = ks ? 0 : 2048;
#pragma unroll
    for (int mt = 0; mt < 2; mt++)
#pragma unroll
        for (int nh = 0; nh < 2; nh++) {
            int q = mt * 2 + nh;
            float4 v = *reinterpret_cast<const float4*>(
                ex + exo + (p * 4 + q) * 128 + lane * 4);
            acc[mt][ntb + nh][0] += v.x;
            acc[mt][ntb + nh][1] += v.y;
            acc[mt][ntb + nh][2] += v.z;
            acc[mt][ntb + nh][3] += v.w;
        }

    // ---- fused epilogue (verified R14-R16) ----
#pragma unroll
    for (int mt = 0; mt < 2; mt++) {
#pragma unroll
        for (int nh = 0; nh < 2; nh++) {
            const int nt = ntb + nh;
            const int R = bm + wm * 32 + mt * 16 + g;
            const int C = bn + wn * 32 + nt * 8 + tig * 2;
            const float b0 = __ldg(&bk[C]);
            const float b1 = __ldg(&bk[C + 1]);

            float2 h0 = *reinterpret_cast<const float2*>(&Hfp[(size_t)R * D_DIM + C]);
            float2 h1 = *reinterpret_cast<const float2*>(&Hfp[(size_t)(R + 8) * D_DIM + C]);
            float o0 = h0.x + 0.1f * fast_tanh(acc[mt][nt][0] + b0);
            float o1 = h0.y + 0.1f * fast_tanh(acc[mt][nt][1] + b1);
            float o2 = h1.x + 0.1f * fast_tanh(acc[mt][nt][2] + b0);
            float o3 = h1.y + 0.1f * fast_tanh(acc[mt][nt][3] + b1);
            *reinterpret_cast<float2*>(&Hout[(size_t)R * D_DIM + C]) = make_float2(o0, o1);
            *reinterpret_cast<float2*>(&Hout[(size_t)(R + 8) * D_DIM + C]) = make_float2(o2, o3);

            const int rb = R >> 4, kb = C >> 4;
            const int c2 = ((nt & 1) << 2) + tig;
            const int lt = g * 4 + (c2 & 3);
            const int wo = (c2 >= 4) ? 2 : 0;
            uint32_t* base = Houth + ((size_t)rb * 64 + kb) * 128 + lt * 4 + wo;
            uint2 u = { pack2(o0, o1), pack2(o2, o3) };
            *reinterpret_cast<uint2*>(base) = u;
        }
    }

    // ---- PDL trigger: epilogue stores issued; let next kernel launch ----
    cudaTriggerProgrammaticLaunchCompletion();
}

extern "C" void kernel_launch(void* const* d_in, const int* in_sizes, int n_in,
                              void* d_out, int out_size)
{
    (void)in_sizes; (void)n_in; (void)out_size;
    const float* x = (const float*)d_in[0];   // [1024, 1024]
    const float* W = (const float*)d_in[1];   // [10, 1024, 1024]
    const float* b = (const float*)d_in[2];   // [10, 1024]

    float* out  = (float*)d_out;
    const size_t BD  = (size_t)D_DIM * D_DIM;
    const size_t BDH = BD / 2;
    float* feat = out;
    float* traj = out + BD;

    uint32_t *wh = nullptr, *hh = nullptr;
    cudaGetSymbolAddress((void**)&wh, g_Wh);
    cudaGetSymbolAddress((void**)&hh, g_Hh);
    uint32_t* hh0 = hh;
    uint32_t* hh1 = hh + BDH;

    cudaFuncSetAttribute(ode_step,
                         cudaFuncAttributeMaxDynamicSharedMemorySize, SMEM_BYTES);

    convert_W<<<4096, 256>>>(W, wh);
    convert_X<<<1024, 256>>>(x, hh0);
    cudaMemcpyAsync(traj, x, BD * sizeof(float), cudaMemcpyDeviceToDevice, 0);

    dim3 grid(D_DIM / BN, D_DIM / BM);   // (16, 16) = 256 CTAs
    dim3 block(THREADS);

    cudaLaunchAttribute attrs[1];
    attrs[0].id = cudaLaunchAttributeProgrammaticStreamSerialization;
    attrs[0].val.programmaticStreamSerializationAllowed = 1;

    cudaLaunchConfig_t cfg = {};
    cfg.gridDim = grid;
    cfg.blockDim = block;
    cfg.dynamicSmemBytes = SMEM_BYTES;
    cfg.stream = 0;
    cfg.attrs = attrs;
    cfg.numAttrs = 1;

    for (int n = 0; n < 100; n++) {
        int k = n / 10;
        uint32_t* hin  = (n & 1) ? hh1 : hh0;
        uint32_t* hnew = (n & 1) ? hh0 : hh1;
        cudaLaunchKernelEx(&cfg, ode_step,
            (const uint32_t*)hin,
            (const uint32_t*)(wh + (size_t)k * BDH),
            (const float*)(traj + (size_t)n * BD),
            (const float*)(b + (size_t)k * D_DIM),
            (float*)(traj + (size_t)(n + 1) * BD),
            (uint32_t*)hnew);
    }

    cudaMemcpyAsync(feat, traj + (size_t)100 * BD, BD * sizeof(float),
                    cudaMemcpyDeviceToDevice, 0);
}